// round 1
// baseline (speedup 1.0000x reference)
#include <cuda_runtime.h>
#include <cstdint>

// Problem constants (fixed by the reference): W=1048576 windows, K=49, C=32.
#define KW 49
#define NC 32
#define CP 16          // channel pairs (f32x2 packing)
#define TW 4           // windows per thread
#define THREADS 256
#define WPB (THREADS * TW)   // 1024 windows per block
#define WTOT 1048576u

__device__ __forceinline__ unsigned long long pack2(float lo, float hi) {
    unsigned long long r;
    asm("mov.b64 %0, {%1, %2};" : "=l"(r) : "f"(lo), "f"(hi));
    return r;
}

__device__ __forceinline__ unsigned long long ffma2(unsigned long long a,
                                                    unsigned long long b,
                                                    unsigned long long c) {
    unsigned long long d;
    asm("fma.rn.f32x2 %0, %1, %2, %3;" : "=l"(d) : "l"(a), "l"(b), "l"(c));
    return d;
}

__global__ __launch_bounds__(THREADS)
void conv_im2col_kernel(const float* __restrict__ x,     // [W, 49]
                        const float* __restrict__ wgt,   // [32, 49] (7x7 flattened)
                        const float* __restrict__ bias,  // [32]
                        float* __restrict__ out)         // [32 * W]
{
    // Packed weights: sw[k][p] = (wgt[2p][k], wgt[2p+1][k]) as f32x2.
    __shared__ unsigned long long sw[KW][CP];
    __shared__ unsigned long long sb[CP];

    const unsigned tid = threadIdx.x;

    for (unsigned i = tid; i < KW * CP; i += THREADS) {
        unsigned k = i / CP, p = i % CP;
        sw[k][p] = pack2(wgt[(2 * p) * KW + k], wgt[(2 * p + 1) * KW + k]);
    }
    if (tid < CP) sb[tid] = pack2(bias[2 * tid], bias[2 * tid + 1]);
    __syncthreads();

    // Accumulators: 4 windows x 16 channel-pairs = 64 f32x2 (128 regs).
    unsigned long long acc[TW][CP];
#pragma unroll
    for (int j = 0; j < TW; j++)
#pragma unroll
        for (int p = 0; p < CP; p++)
            acc[j][p] = sb[p];

    const unsigned base = blockIdx.x * WPB + tid;   // window of chunk j=0

    // Row base offsets (elements). W*K = 51.4M < 2^31, so 32-bit is safe.
    unsigned row[TW];
#pragma unroll
    for (int j = 0; j < TW; j++) row[j] = (base + j * THREADS) * KW;

#pragma unroll 7
    for (int k = 0; k < KW; k++) {
        unsigned long long xv[TW];
#pragma unroll
        for (int j = 0; j < TW; j++) {
            float v = x[row[j] + k];
            xv[j] = pack2(v, v);   // duplicate for channel-pair FFMA2
        }
#pragma unroll
        for (int p = 0; p < CP; p++) {
            unsigned long long w2 = sw[k][p];
#pragma unroll
            for (int j = 0; j < TW; j++)
                acc[j][p] = ffma2(xv[j], w2, acc[j][p]);
        }
    }

    // Store: out[c * W + w]; lanes are consecutive w -> coalesced STG.32.
#pragma unroll
    for (int j = 0; j < TW; j++) {
        unsigned w = base + j * THREADS;
#pragma unroll
        for (int p = 0; p < CP; p++) {
            float lo, hi;
            asm("mov.b64 {%0, %1}, %2;" : "=f"(lo), "=f"(hi) : "l"(acc[j][p]));
            out[(unsigned)(2 * p) * WTOT + w]     = lo;
            out[(unsigned)(2 * p + 1) * WTOT + w] = hi;
        }
    }
}

extern "C" void kernel_launch(void* const* d_in, const int* in_sizes, int n_in,
                              void* d_out, int out_size) {
    const float* x    = (const float*)d_in[0];   // enc_x [1048576, 49]
    const float* wgt  = (const float*)d_in[1];   // weight [32, 7, 7]
    const float* bias = (const float*)d_in[2];   // bias [32]
    float* out = (float*)d_out;                  // [32 * 1048576]

    const unsigned nblocks = WTOT / WPB;         // 1024
    conv_im2col_kernel<<<nblocks, THREADS>>>(x, wgt, bias, out);
}

// round 2
// speedup vs baseline: 1.2130x; 1.2130x over previous
#include <cuda_runtime.h>
#include <cstdint>

// W=1048576 windows, K=49, C=32 output channels.
#define KW 49
#define CP 16          // channel pairs (f32x2 packing)
#define TW 2           // windows per thread
#define THREADS 128
#define WPB (THREADS * TW)   // 256 windows per block
#define WTOT 1048576u

__device__ __forceinline__ unsigned long long pack2(float lo, float hi) {
    unsigned long long r;
    asm("mov.b64 %0, {%1, %2};" : "=l"(r) : "f"(lo), "f"(hi));
    return r;
}

__device__ __forceinline__ unsigned long long ffma2(unsigned long long a,
                                                    unsigned long long b,
                                                    unsigned long long c) {
    unsigned long long d;
    asm("fma.rn.f32x2 %0, %1, %2, %3;" : "=l"(d) : "l"(a), "l"(b), "l"(c));
    return d;
}

__global__ __launch_bounds__(THREADS, 4)
void conv_im2col_kernel(const float* __restrict__ x,     // [W, 49]
                        const float* __restrict__ wgt,   // [32, 49]
                        const float* __restrict__ bias,  // [32]
                        float* __restrict__ out)         // [32 * W]
{
    // Weights packed 4 channels per 16B: sw[k][q] = ((w[4q,k],w[4q+1,k]),(w[4q+2,k],w[4q+3,k]))
    __shared__ ulonglong2 sw[KW][CP / 2];   // 49 * 8 * 16B = 6272 B
    __shared__ unsigned long long sb[CP];

    const unsigned tid = threadIdx.x;

    {
        unsigned long long* swf = reinterpret_cast<unsigned long long*>(&sw[0][0]);
        for (unsigned i = tid; i < KW * CP; i += THREADS) {
            unsigned k = i / CP, p = i % CP;
            swf[k * CP + p] = pack2(wgt[(2 * p) * KW + k], wgt[(2 * p + 1) * KW + k]);
        }
        if (tid < CP) sb[tid] = pack2(bias[2 * tid], bias[2 * tid + 1]);
    }
    __syncthreads();

    // 2 windows x 16 channel-pairs = 32 f32x2 accumulators (64 regs).
    unsigned long long acc0[CP], acc1[CP];
#pragma unroll
    for (int p = 0; p < CP; p++) { acc0[p] = sb[p]; acc1[p] = sb[p]; }

    const unsigned w0 = blockIdx.x * WPB + tid;   // window for chunk 0
    const unsigned w1 = w0 + THREADS;             // window for chunk 1
    const unsigned row0 = w0 * KW;
    const unsigned row1 = w1 * KW;

#pragma unroll 7
    for (int k = 0; k < KW; k++) {
        float v0 = x[row0 + k];
        float v1 = x[row1 + k];
        unsigned long long x0 = pack2(v0, v0);
        unsigned long long x1 = pack2(v1, v1);
#pragma unroll
        for (int q = 0; q < CP / 2; q++) {
            ulonglong2 w2 = sw[k][q];              // LDS.128: two channel-pairs
            acc0[2 * q]     = ffma2(x0, w2.x, acc0[2 * q]);
            acc1[2 * q]     = ffma2(x1, w2.x, acc1[2 * q]);
            acc0[2 * q + 1] = ffma2(x0, w2.y, acc0[2 * q + 1]);
            acc1[2 * q + 1] = ffma2(x1, w2.y, acc1[2 * q + 1]);
        }
    }

    // Coalesced stores: out[c * W + w], lanes consecutive in w.
#pragma unroll
    for (int p = 0; p < CP; p++) {
        float lo, hi;
        asm("mov.b64 {%0, %1}, %2;" : "=f"(lo), "=f"(hi) : "l"(acc0[p]));
        out[(unsigned)(2 * p) * WTOT + w0]     = lo;
        out[(unsigned)(2 * p + 1) * WTOT + w0] = hi;
        asm("mov.b64 {%0, %1}, %2;" : "=f"(lo), "=f"(hi) : "l"(acc1[p]));
        out[(unsigned)(2 * p) * WTOT + w1]     = lo;
        out[(unsigned)(2 * p + 1) * WTOT + w1] = hi;
    }
}

extern "C" void kernel_launch(void* const* d_in, const int* in_sizes, int n_in,
                              void* d_out, int out_size) {
    const float* x    = (const float*)d_in[0];   // enc_x [1048576, 49]
    const float* wgt  = (const float*)d_in[1];   // weight [32, 7, 7]
    const float* bias = (const float*)d_in[2];   // bias [32]
    float* out = (float*)d_out;

    const unsigned nblocks = WTOT / WPB;         // 4096
    conv_im2col_kernel<<<nblocks, THREADS>>>(x, wgt, bias, out);
}

// round 3
// speedup vs baseline: 1.4349x; 1.1829x over previous
#include <cuda_runtime.h>
#include <cstdint>

// W=1048576 windows, K=49, C=32 output channels.
#define KW 49
#define CP 16              // channel pairs (f32x2 packing)
#define THREADS 128
#define WPB 256            // windows per block (2 per thread)
#define WTOT 1048576u

// dynamic smem layout: sx[WPB*KW] floats | sw[KW][CP/2] ulonglong2 | sb[CP] u64
#define SX_FLOATS (WPB * KW)                       // 12544
#define SX_BYTES  (SX_FLOATS * 4)                  // 50176
#define SW_BYTES  (KW * (CP / 2) * 16)             // 6272
#define SMEM_BYTES (SX_BYTES + SW_BYTES + CP * 8)  // 56576

__device__ __forceinline__ unsigned long long pack2(float lo, float hi) {
    unsigned long long r;
    asm("mov.b64 %0, {%1, %2};" : "=l"(r) : "f"(lo), "f"(hi));
    return r;
}

__device__ __forceinline__ unsigned long long ffma2(unsigned long long a,
                                                    unsigned long long b,
                                                    unsigned long long c) {
    unsigned long long d;
    asm("fma.rn.f32x2 %0, %1, %2, %3;" : "=l"(d) : "l"(a), "l"(b), "l"(c));
    return d;
}

__global__ __launch_bounds__(THREADS, 4)
void conv_im2col_kernel(const float* __restrict__ x,     // [W, 49]
                        const float* __restrict__ wgt,   // [32, 49]
                        const float* __restrict__ bias,  // [32]
                        float* __restrict__ out)         // [32 * W]
{
    extern __shared__ __align__(16) unsigned char smem_raw[];
    float*              sx = reinterpret_cast<float*>(smem_raw);
    ulonglong2*         sw = reinterpret_cast<ulonglong2*>(smem_raw + SX_BYTES);
    unsigned long long* sb = reinterpret_cast<unsigned long long*>(smem_raw + SX_BYTES + SW_BYTES);

    const unsigned tid = threadIdx.x;

    // --- Stage weights (packed channel pairs) and bias ---
    {
        unsigned long long* swf = reinterpret_cast<unsigned long long*>(sw);
        for (unsigned i = tid; i < KW * CP; i += THREADS) {
            unsigned k = i / CP, p = i % CP;
            swf[k * CP + p] = pack2(wgt[(2 * p) * KW + k], wgt[(2 * p + 1) * KW + k]);
        }
        if (tid < CP) sb[tid] = pack2(bias[2 * tid], bias[2 * tid + 1]);
    }

    // --- Stage x tile: 256 contiguous rows -> fully coalesced LDG.128 ---
    {
        const float4* src = reinterpret_cast<const float4*>(
            x + (size_t)blockIdx.x * (WPB * KW));
        float4* dst = reinterpret_cast<float4*>(sx);
        for (unsigned i = tid; i < SX_FLOATS / 4; i += THREADS)   // 3136 float4
            dst[i] = src[i];
    }
    __syncthreads();

    // --- Accumulators: 2 windows x 16 channel-pairs (64 regs) ---
    unsigned long long acc0[CP], acc1[CP];
#pragma unroll
    for (int p = 0; p < CP; p++) { acc0[p] = sb[p]; acc1[p] = sb[p]; }

    const float* r0 = sx + tid * KW;             // window tid
    const float* r1 = sx + (tid + THREADS) * KW; // window tid+128

#pragma unroll 7
    for (int k = 0; k < KW; k++) {
        float v0 = r0[k];                        // LDS.32, conflict-free (stride 49)
        float v1 = r1[k];
        unsigned long long x0 = pack2(v0, v0);
        unsigned long long x1 = pack2(v1, v1);
#pragma unroll
        for (int q = 0; q < CP / 2; q++) {
            ulonglong2 w2 = sw[k * (CP / 2) + q]; // LDS.128 broadcast
            acc0[2 * q]     = ffma2(x0, w2.x, acc0[2 * q]);
            acc1[2 * q]     = ffma2(x1, w2.x, acc1[2 * q]);
            acc0[2 * q + 1] = ffma2(x0, w2.y, acc0[2 * q + 1]);
            acc1[2 * q + 1] = ffma2(x1, w2.y, acc1[2 * q + 1]);
        }
    }

    // --- Coalesced stores: out[c * W + w] ---
    const unsigned w0 = blockIdx.x * WPB + tid;
    const unsigned w1 = w0 + THREADS;
#pragma unroll
    for (int p = 0; p < CP; p++) {
        float lo, hi;
        asm("mov.b64 {%0, %1}, %2;" : "=f"(lo), "=f"(hi) : "l"(acc0[p]));
        out[(unsigned)(2 * p) * WTOT + w0]     = lo;
        out[(unsigned)(2 * p + 1) * WTOT + w0] = hi;
        asm("mov.b64 {%0, %1}, %2;" : "=f"(lo), "=f"(hi) : "l"(acc1[p]));
        out[(unsigned)(2 * p) * WTOT + w1]     = lo;
        out[(unsigned)(2 * p + 1) * WTOT + w1] = hi;
    }
}

extern "C" void kernel_launch(void* const* d_in, const int* in_sizes, int n_in,
                              void* d_out, int out_size) {
    const float* x    = (const float*)d_in[0];   // enc_x [1048576, 49]
    const float* wgt  = (const float*)d_in[1];   // weight [32, 7, 7]
    const float* bias = (const float*)d_in[2];   // bias [32]
    float* out = (float*)d_out;

    cudaFuncSetAttribute(conv_im2col_kernel,
                         cudaFuncAttributeMaxDynamicSharedMemorySize, SMEM_BYTES);

    const unsigned nblocks = WTOT / WPB;         // 4096
    conv_im2col_kernel<<<nblocks, THREADS, SMEM_BYTES>>>(x, wgt, bias, out);
}